// round 11
// baseline (speedup 1.0000x reference)
#include <cuda_runtime.h>
#include <cstddef>

// Problem constants
#define NX 64
#define NU 32
#define NY 32
#define NW 64
#define BB 256
#define TT 2048

// Fused weight table gW[160][160] (row-major):
//  rows   0..63  (z):  [ C2*t_inv | D21*t_inv | (unused) ]
//  rows  64..127 (x):  [ Yinv^T A | Yinv^T B1 | Yinv^T B2]
//  rows 128..159 (y):  [ C1       | D11       | D12      ]
__device__ float gW[160 * 160];

// Per-thread packed weights gWT[s][96]:
//  s in [0,128)   : z half: row=s>>1, h=s&1.  i0..7: x-chunks c=h+2i;
//                   i8..11: u-chunks c=16+h+2(i-8).                (48 floats)
//  s in [128,256) : x half: idx=s-128, row=64+(idx>>1), h=idx&1.
//                   i0..7: x c=h+2i; i8..11: u c=16+h+2(i-8);
//                   i12..19: w c=24+h+2(i-12).                     (80 floats)
//  s in [256,320) : y half (for y-pass; v layout [x|w|u]):
//                   idx=s-256, row=128+(idx>>1), h.
//                   i0..7: C1 c=h+2i; i8..15: D12 c=24+h+2(i-8);
//                   i16..19: D11 c=16+h+2(i-16).                   (80 floats)
__device__ float gWT[320 * 96];

// Trajectory stream for the decoupled y-pass: gVseq[b][t][128] = [x_t | w_t].
// Slot t+1's x written at step t; slot TT used only as scratch target.
__device__ __align__(16) float gVseq[(size_t)BB * (TT + 1) * 128];

// ---------------------------------------------------------------------------
// Setup: Newton-Schulz inverse of Y, fold Y_inv and t_inv into gW, pack gWT.
// ---------------------------------------------------------------------------
__global__ void __launch_bounds__(512, 1)
setup_kernel(const float* __restrict__ Y,
             const float* __restrict__ lambdas,
             const float* __restrict__ A,
             const float* __restrict__ B1,
             const float* __restrict__ B2,
             const float* __restrict__ C1,
             const float* __restrict__ D11,
             const float* __restrict__ D12,
             const float* __restrict__ C2,
             const float* __restrict__ D21)
{
    __shared__ float sX[64 * 64];
    __shared__ float sQ[64 * 64];
    __shared__ float sN[64 * 64];
    const int tid = threadIdx.x;   // 512 threads

    #pragma unroll
    for (int s = 0; s < 8; s++) {
        int e = tid + 512 * s;
        int i = e >> 6, j = e & 63;
        sX[e] = ((i == j) ? 2.0f : 0.0f) - Y[e];
    }
    __syncthreads();

    for (int it = 0; it < 4; it++) {
        #pragma unroll
        for (int s = 0; s < 8; s++) {
            int e = tid + 512 * s;
            int i = e >> 6, j = e & 63;
            float acc = 0.0f;
            #pragma unroll 8
            for (int k = 0; k < 64; k++)
                acc += Y[i * 64 + k] * sX[k * 64 + j];
            sQ[e] = ((i == j) ? 2.0f : 0.0f) - acc;
        }
        __syncthreads();
        #pragma unroll
        for (int s = 0; s < 8; s++) {
            int e = tid + 512 * s;
            int i = e >> 6, j = e & 63;
            float acc = 0.0f;
            #pragma unroll 8
            for (int k = 0; k < 64; k++)
                acc += sX[i * 64 + k] * sQ[k * 64 + j];
            sN[e] = acc;
        }
        __syncthreads();
        #pragma unroll
        for (int s = 0; s < 8; s++) {
            int e = tid + 512 * s;
            sX[e] = sN[e];
        }
        __syncthreads();
    }
    // sX = Y^{-1}

    for (int e = tid; e < 64 * 64; e += 512) {
        int j = e >> 6, k2 = e & 63;
        gW[j * 160 + k2] = C2[j * 64 + k2] / lambdas[j];
    }
    for (int e = tid; e < 64 * 32; e += 512) {
        int j = e >> 5, m = e & 31;
        gW[j * 160 + 64 + m] = D21[j * 32 + m] / lambdas[j];
    }
    for (int e = tid; e < 64 * 64; e += 512) {
        int j = e >> 6, k2 = e & 63;
        float sA = 0.0f, sB2 = 0.0f;
        #pragma unroll 8
        for (int i = 0; i < 64; i++) {
            float yi = sX[i * 64 + j];
            sA  += yi * A[i * 64 + k2];
            sB2 += yi * B2[i * 64 + k2];
        }
        gW[(64 + j) * 160 + k2]      = sA;
        gW[(64 + j) * 160 + 96 + k2] = sB2;
    }
    for (int e = tid; e < 64 * 32; e += 512) {
        int j = e >> 5, m = e & 31;
        float s = 0.0f;
        #pragma unroll 8
        for (int i = 0; i < 64; i++) s += sX[i * 64 + j] * B1[i * 32 + m];
        gW[(64 + j) * 160 + 64 + m] = s;
    }
    for (int e = tid; e < 32 * 64; e += 512) {
        int j = e >> 6, k2 = e & 63;
        gW[(128 + j) * 160 + k2]      = C1[j * 64 + k2];
        gW[(128 + j) * 160 + 96 + k2] = D12[j * 64 + k2];
    }
    for (int e = tid; e < 32 * 32; e += 512) {
        int j = e >> 5, m = e & 31;
        gW[(128 + j) * 160 + 64 + m] = D11[j * 32 + m];
    }
    __syncthreads();

    // --- pack gWT ---
    for (int s = tid; s < 320; s += 512) {
        if (s < 128) {
            int row = s >> 1, h = s & 1;
            for (int i = 0; i < 8; i++) {
                int c = h + 2 * i;
                #pragma unroll
                for (int j = 0; j < 4; j++)
                    gWT[s * 96 + 4 * i + j] = gW[row * 160 + 4 * c + j];
            }
            for (int i = 8; i < 12; i++) {
                int c = 16 + h + 2 * (i - 8);
                #pragma unroll
                for (int j = 0; j < 4; j++)
                    gWT[s * 96 + 4 * i + j] = gW[row * 160 + 4 * c + j];
            }
        } else if (s < 256) {
            int idx = s - 128, row = 64 + (idx >> 1), h = idx & 1;
            for (int i = 0; i < 20; i++) {
                int c;
                if (i < 8)       c = h + 2 * i;
                else if (i < 12) c = 16 + h + 2 * (i - 8);
                else             c = 24 + h + 2 * (i - 12);
                #pragma unroll
                for (int j = 0; j < 4; j++)
                    gWT[s * 96 + 4 * i + j] = gW[row * 160 + 4 * c + j];
            }
        } else {
            int idx = s - 256, row = 128 + (idx >> 1), h = idx & 1;
            for (int i = 0; i < 20; i++) {
                int c;
                if (i < 8)       c = h + 2 * i;             // C1   -> v[0:64)
                else if (i < 16) c = 24 + h + 2 * (i - 8);  // D12  -> v[64:128)
                else             c = 16 + h + 2 * (i - 16); // D11  -> v[128:160)
                #pragma unroll
                for (int j = 0; j < 4; j++)
                    gWT[s * 96 + 4 * i + j] = gW[row * 160 + 4 * c + j];
            }
        }
    }
}

// ---------------------------------------------------------------------------
// helpers
// ---------------------------------------------------------------------------
__device__ __forceinline__ float2 u64_as_f2(unsigned long long x) {
    float2 r;
    asm("mov.b64 {%0, %1}, %2;" : "=f"(r.x), "=f"(r.y) : "l"(x));
    return r;
}
#define FFMA2(acc, w, vv) \
    asm("fma.rn.f32x2 %0, %1, %2, %0;" : "+l"(acc) : "l"(w), "l"(vv))
#define ADDF2(d, a, b) \
    asm("add.rn.f32x2 %0, %1, %2;" : "=l"(d) : "l"(a), "l"(b))
#define BARB(id) asm volatile("bar.sync %0, 256;" :: "r"(id) : "memory")

__device__ __forceinline__ float fast_tanh(float x) {
    float e;
    asm("ex2.approx.f32 %0, %1;" : "=f"(e) : "f"(x * 2.8853900817779268f));
    return 1.0f - __fdividef(2.0f, e + 1.0f);
}

// ---------------------------------------------------------------------------
// Sequential kernel: 128 CTAs x 512 threads, 2 batch chains per CTA.
// Per batch (256 threads = 8 warps): 4 z-half warps + 4 x-half warps.
// All rows split across adjacent lane pairs; one LDS.128 serves both halves
// (adjacent 16B chunks, conflict-free). y is NOT computed here: [x_t|w_t]
// streams to gVseq for the weight-persistent y-pass.
// Roles: batch = wid&1; z = wid>=8; x = wid<8 (widx0 x warp = u stager).
// ---------------------------------------------------------------------------
__global__ void __launch_bounds__(512, 1)
rnn_kernel(const float* __restrict__ xpred, float* __restrict__ out, int write_xfinal)
{
    __shared__ __align__(16) float sv[2 * 192];

    const int tid  = threadIdx.x;
    const int wid  = tid >> 5;
    const int lane = tid & 31;

    const int isZ   = (wid >= 8);
    const int batch = wid & 1;
    const int widx  = (isZ ? (wid - 8) : wid) >> 1;
    const int idx   = widx * 32 + lane;     // 0..127
    const int row   = idx >> 1;             // z row / x state row 0..63
    const int h     = idx & 1;

    float* vx = sv + batch * 192;           // x_t   [64]
    float* vw = vx + 64;                    // w_t   [64]
    float* vu = vx + 128;                   // u     [2][32]
    const int bg = blockIdx.x * 2 + batch;
    const float* uptr = xpred + (size_t)bg * TT * NU;
    float* gv = gVseq + (size_t)bg * (TT + 1) * 128;
    const int barid = batch + 1;
    const bool stager = (!isZ && widx == 0);

    if (isZ) {
        // ================= Z half: 8 crit chunks + 4 u chunks =============
        unsigned long long wreg[24];
        {
            const unsigned long long* grow = (const unsigned long long*)(gWT + idx * 96);
            #pragma unroll
            for (int i = 0; i < 24; i++) wreg[i] = grow[i];
        }

        // init x0 = 0 (smem + gVseq slot 0)
        if (h == 0) {
            vx[row] = 0.0f;
            gv[row] = 0.0f;
        }
        BARB(barid);    // u_0 staged

        const float* vxh = vx + 4 * h;

        // prologue: u-partial for t=0 from vu buf0
        unsigned long long u0;
        {
            const float* ub = vu + 4 * h;
            unsigned long long b0 = 0ull, b1 = 0ull;
            #pragma unroll
            for (int i = 0; i < 4; i += 2) {
                ulonglong2 q0 = *(const ulonglong2*)(ub + 8 * i);
                ulonglong2 q1 = *(const ulonglong2*)(ub + 8 * i + 8);
                FFMA2(b0, wreg[16 + 2*i],   q0.x);
                FFMA2(b1, wreg[16 + 2*i+1], q0.y);
                FFMA2(b0, wreg[16 + 2*i+2], q1.x);
                FFMA2(b1, wreg[16 + 2*i+3], q1.y);
            }
            ADDF2(u0, b0, b1);
        }

        for (int t = 0; t < TT; t++) {
            // ---- Phase A: x-part (8 chunks) + tanh, publish + stream w ----
            unsigned long long a0=0ull,a1=0ull,a2=0ull,a3=0ull;
            #pragma unroll
            for (int i = 0; i < 8; i += 2) {
                ulonglong2 v0 = *(const ulonglong2*)(vxh + 8 * i);
                ulonglong2 v1 = *(const ulonglong2*)(vxh + 8 * i + 8);
                FFMA2(a0, wreg[2*i],   v0.x);
                FFMA2(a1, wreg[2*i+1], v0.y);
                FFMA2(a2, wreg[2*i+2], v1.x);
                FFMA2(a3, wreg[2*i+3], v1.y);
            }
            ADDF2(a0, a0, a2); ADDF2(a1, a1, a3);
            ADDF2(a0, a0, a1); ADDF2(a0, a0, u0);
            float2 p = u64_as_f2(a0);
            float zacc = p.x + p.y;
            zacc += __shfl_xor_sync(0xffffffffu, zacc, 1);
            float w = fast_tanh(zacc);
            if (h == 0) {
                vw[row] = w;                            // publish w_t
                gv[(size_t)t * 128 + 64 + row] = w;     // stream w_t
            }
            BARB(barid);   // barA

            // ---- Phase B: u-partial for t+1 ----
            {
                const float* ub = vu + ((t + 1) & 1) * 32 + 4 * h;
                unsigned long long b0 = 0ull, b1 = 0ull;
                #pragma unroll
                for (int i = 0; i < 4; i += 2) {
                    ulonglong2 q0 = *(const ulonglong2*)(ub + 8 * i);
                    ulonglong2 q1 = *(const ulonglong2*)(ub + 8 * i + 8);
                    FFMA2(b0, wreg[16 + 2*i],   q0.x);
                    FFMA2(b1, wreg[16 + 2*i+1], q0.y);
                    FFMA2(b0, wreg[16 + 2*i+2], q1.x);
                    FFMA2(b1, wreg[16 + 2*i+3], q1.y);
                }
                ADDF2(u0, b0, b1);
            }
            BARB(barid);   // barB: x_{t+1}, u staged
        }

        if (write_xfinal && h == 0) {
            out[(size_t)BB * TT * NY + (size_t)bg * NX + row] = vx[row];
        }
    } else {
        // ================= X half: 8+8 crit chunks + 4 u chunks ===========
        unsigned long long wreg[40];
        {
            const unsigned long long* grow = (const unsigned long long*)(gWT + (128 + idx) * 96);
            #pragma unroll
            for (int i = 0; i < 40; i++) wreg[i] = grow[i];
        }

        // stage u_0; u_next = u_1
        float u_next = 0.0f;
        if (stager) {
            vu[lane] = uptr[lane];
            u_next = uptr[NU + lane];
        }
        BARB(barid);

        const float* vxh = vx + 4 * h;
        const float* vwh = vw + 4 * h;

        // prologue: u-partial for t=0
        unsigned long long u0;
        {
            const float* ub = vu + 4 * h;
            unsigned long long b0 = 0ull, b1 = 0ull;
            #pragma unroll
            for (int i = 0; i < 4; i += 2) {
                ulonglong2 q0 = *(const ulonglong2*)(ub + 8 * i);
                ulonglong2 q1 = *(const ulonglong2*)(ub + 8 * i + 8);
                FFMA2(b0, wreg[16 + 2*i],   q0.x);
                FFMA2(b1, wreg[16 + 2*i+1], q0.y);
                FFMA2(b0, wreg[16 + 2*i+2], q1.x);
                FFMA2(b1, wreg[16 + 2*i+3], q1.y);
            }
            ADDF2(u0, b0, b1);
        }

        for (int t = 0; t < TT; t++) {
            // ---- Phase A: x-part (8 chunks); stager refreshes u ----
            unsigned long long a0=0ull,a1=0ull,a2=0ull,a3=0ull;
            #pragma unroll
            for (int i = 0; i < 8; i += 2) {
                ulonglong2 v0 = *(const ulonglong2*)(vxh + 8 * i);
                ulonglong2 v1 = *(const ulonglong2*)(vxh + 8 * i + 8);
                FFMA2(a0, wreg[2*i],   v0.x);
                FFMA2(a1, wreg[2*i+1], v0.y);
                FFMA2(a2, wreg[2*i+2], v1.x);
                FFMA2(a3, wreg[2*i+3], v1.y);
            }
            if (stager) {
                vu[((t + 1) & 1) * 32 + lane] = u_next;   // u_{t+1}
                if (t + 2 < TT) u_next = uptr[(size_t)(t + 2) * NU + lane];
            }
            BARB(barid);   // barA: w_t visible

            // ---- Phase B: w-part (8 chunks) + publish + stream x ----
            #pragma unroll
            for (int i = 0; i < 8; i += 2) {
                ulonglong2 v0 = *(const ulonglong2*)(vwh + 8 * i);
                ulonglong2 v1 = *(const ulonglong2*)(vwh + 8 * i + 8);
                FFMA2(a0, wreg[24 + 2*i],   v0.x);
                FFMA2(a1, wreg[24 + 2*i+1], v0.y);
                FFMA2(a2, wreg[24 + 2*i+2], v1.x);
                FFMA2(a3, wreg[24 + 2*i+3], v1.y);
            }
            ADDF2(a0, a0, a2); ADDF2(a1, a1, a3);
            ADDF2(a0, a0, a1); ADDF2(a0, a0, u0);
            float2 p = u64_as_f2(a0);
            float acc = p.x + p.y;
            acc += __shfl_xor_sync(0xffffffffu, acc, 1);
            if (h == 0) {
                vx[row] = acc;                             // publish x_{t+1}
                gv[(size_t)(t + 1) * 128 + row] = acc;     // stream x_{t+1}
            }

            // u-partial for t+1
            {
                const float* ub = vu + ((t + 1) & 1) * 32 + 4 * h;
                unsigned long long b0 = 0ull, b1 = 0ull;
                #pragma unroll
                for (int i = 0; i < 4; i += 2) {
                    ulonglong2 q0 = *(const ulonglong2*)(ub + 8 * i);
                    ulonglong2 q1 = *(const ulonglong2*)(ub + 8 * i + 8);
                    FFMA2(b0, wreg[16 + 2*i],   q0.x);
                    FFMA2(b1, wreg[16 + 2*i+1], q0.y);
                    FFMA2(b0, wreg[16 + 2*i+2], q1.x);
                    FFMA2(b1, wreg[16 + 2*i+3], q1.y);
                }
                ADDF2(u0, b0, b1);
            }
            BARB(barid);   // barB
        }
    }
}

// ---------------------------------------------------------------------------
// y-pass: weight-persistent. Grid (BB, 4), 256 threads. Each CTA: one batch,
// 512 timesteps (128 rounds of 4). Thread = (g = t-slot, j = y row, h = half);
// y half-row (80 floats) in registers; v = [x|w|u] staged per round in smem.
// ---------------------------------------------------------------------------
__global__ void __launch_bounds__(256, 4)
ypass_kernel(const float* __restrict__ xpred, float* __restrict__ out)
{
    __shared__ __align__(16) float sv2[4 * 160];

    const int b   = blockIdx.x;
    const int seg = blockIdx.y;       // 0..3: timestep segment
    const int tid = threadIdx.x;
    const int g = tid >> 6;           // 0..3
    const int q = tid & 63;
    const int j = q >> 1, h = q & 1;

    const float* gv = gVseq + (size_t)b * (TT + 1) * 128;
    const float* uptr = xpred + (size_t)b * TT * NU;
    float* yout = out + (size_t)b * TT * NY;

    unsigned long long wreg[40];
    {
        const unsigned long long* grow = (const unsigned long long*)(gWT + (256 + q) * 96);
        #pragma unroll
        for (int i = 0; i < 40; i++) wreg[i] = grow[i];
    }

    const float* vh = sv2 + g * 160 + 4 * h;

    for (int rnd = 0; rnd < TT / 4 / 4; rnd++) {
        const int t0 = seg * (TT / 4) + rnd * 4;

        // stage 4 timesteps: [x|w](128) from gVseq + u(32) from xpred
        for (int e = tid; e < 160; e += 256) {
            int tl = e / 40, k = e - tl * 40;
            int t = t0 + tl;
            float4 val;
            float* dst;
            if (k < 32) {
                val = *(const float4*)(gv + (size_t)t * 128 + 4 * k);
                dst = sv2 + tl * 160 + 4 * k;
            } else {
                val = *(const float4*)(uptr + (size_t)t * NU + 4 * (k - 32));
                dst = sv2 + tl * 160 + 128 + 4 * (k - 32);
            }
            *(float4*)dst = val;
        }
        __syncthreads();

        unsigned long long a0=0ull,a1=0ull,a2=0ull,a3=0ull;
        #pragma unroll
        for (int i = 0; i < 20; i += 2) {
            ulonglong2 v0 = *(const ulonglong2*)(vh + 8 * i);
            ulonglong2 v1 = *(const ulonglong2*)(vh + 8 * i + 8);
            FFMA2(a0, wreg[2*i],   v0.x);
            FFMA2(a1, wreg[2*i+1], v0.y);
            FFMA2(a2, wreg[2*i+2], v1.x);
            FFMA2(a3, wreg[2*i+3], v1.y);
        }
        ADDF2(a0, a0, a2); ADDF2(a1, a1, a3); ADDF2(a0, a0, a1);
        float2 p = u64_as_f2(a0);
        float acc = p.x + p.y;
        acc += __shfl_xor_sync(0xffffffffu, acc, 1);
        if (h == 0) yout[(size_t)(t0 + g) * NY + j] = acc;
        __syncthreads();
    }
}

// ---------------------------------------------------------------------------
extern "C" void kernel_launch(void* const* d_in, const int* in_sizes, int n_in,
                              void* d_out, int out_size)
{
    const float* xpred   = (const float*)d_in[0];
    const float* Y       = (const float*)d_in[1];
    const float* lambdas = (const float*)d_in[2];
    const float* A       = (const float*)d_in[3];
    const float* B1      = (const float*)d_in[4];
    const float* B2      = (const float*)d_in[5];
    const float* C1      = (const float*)d_in[6];
    const float* D11     = (const float*)d_in[7];
    const float* D12     = (const float*)d_in[8];
    const float* C2      = (const float*)d_in[9];
    const float* D21     = (const float*)d_in[10];

    (void)in_sizes; (void)n_in;

    setup_kernel<<<1, 512>>>(Y, lambdas, A, B1, B2, C1, D11, D12, C2, D21);

    int write_xfinal = (out_size >= BB * TT * NY + BB * NX) ? 1 : 0;
    rnn_kernel<<<BB / 2, 512>>>(xpred, (float*)d_out, write_xfinal);

    dim3 ygrid(BB, 4);
    ypass_kernel<<<ygrid, 256>>>(xpred, (float*)d_out);
}

// round 12
// speedup vs baseline: 1.1186x; 1.1186x over previous
#include <cuda_runtime.h>
#include <cstddef>

// Problem constants
#define NX 64
#define NU 32
#define NY 32
#define NW 64
#define BB 256
#define TT 2048

// Fused weight table gW[160][192] (row-major, stride 192):
//  z rows 0..63 :  [ Gzx(64) | Gzw(64) | Gzu(32) | D21t(32) ]
//    Gzx=C2t@Atil, Gzw=C2t@B2til, Gzu=C2t@B1til, C2t=C2/lam, D21t=D21/lam
//  x rows 64..127: [ Atil(64) | B2til(64) | B1til(32) | pad ]
//  y rows 128..159:[ C1(64)   | D12(64)   | D11(32)   | pad ]
__device__ float gW[160 * 192];

// Per-thread packed weights gWT[s][96] (chunk = 4 floats = 2 u64):
//  s in [0,128):   z half: row=s>>1, h=s&1. i0..15: c=h+2i (crit [Gzx|Gzw]);
//                  i16..19: c=32+h+2(i-16) (Gzu); i20..23: c=40+h+2(i-20) (D21t)
//  s in [128,256): x half: idx=s-128, row=64+(idx>>1), h=idx&1.
//                  i0..15 crit [Atil|B2til]; i16..19: B1til
//  s in [256,320): y half: idx=s-256, row=128+(idx>>1).
//                  i0..15 crit [C1|D12] (v=[x|w]); i16..19: D11 (v u-part)
__device__ float gWT[320 * 96];

// Trajectory stream: gVseq[b][t][128] = [x_t | w_t], t in [0,TT] (TT = scratch)
__device__ __align__(16) float gVseq[(size_t)BB * (TT + 1) * 128];

// ---------------------------------------------------------------------------
// Setup: Newton-Schulz inverse (3 iters, vectorized), fused weights, pack.
// ---------------------------------------------------------------------------
__global__ void __launch_bounds__(512, 1)
setup_kernel(const float* __restrict__ Y,
             const float* __restrict__ lambdas,
             const float* __restrict__ A,
             const float* __restrict__ B1,
             const float* __restrict__ B2,
             const float* __restrict__ C1,
             const float* __restrict__ D11,
             const float* __restrict__ D12,
             const float* __restrict__ C2,
             const float* __restrict__ D21)
{
    __shared__ float sX[4096];   // Yinv
    __shared__ float sQ[4096];   // scratch -> H
    __shared__ float sN[4096];   // scratch -> Yinv^T
    const int tid = threadIdx.x;
    const int r8  = tid >> 3;    // row 0..63
    const int g8  = tid & 7;     // col group of 8

    // X0 = 2I - Y
    for (int e = tid; e < 4096; e += 512) {
        int i = e >> 6, j = e & 63;
        sX[e] = ((i == j) ? 2.0f : 0.0f) - Y[e];
    }
    __syncthreads();

    // Newton-Schulz: X <- X(2I - Y X), 3 iters (E0~0.026 -> 2e-13)
    for (int it = 0; it < 3; it++) {
        float acc[8];
        #pragma unroll
        for (int m = 0; m < 8; m++) acc[m] = 0.0f;
        for (int k = 0; k < 64; k++) {
            float a = Y[r8 * 64 + k];
            float4 x0 = ((const float4*)(sX + k * 64))[g8 * 2];
            float4 x1 = ((const float4*)(sX + k * 64))[g8 * 2 + 1];
            acc[0] += a * x0.x; acc[1] += a * x0.y; acc[2] += a * x0.z; acc[3] += a * x0.w;
            acc[4] += a * x1.x; acc[5] += a * x1.y; acc[6] += a * x1.z; acc[7] += a * x1.w;
        }
        #pragma unroll
        for (int m = 0; m < 8; m++) {
            int j = g8 * 8 + m;
            sQ[r8 * 64 + j] = ((j == r8) ? 2.0f : 0.0f) - acc[m];
        }
        __syncthreads();
        #pragma unroll
        for (int m = 0; m < 8; m++) acc[m] = 0.0f;
        for (int k = 0; k < 64; k++) {
            float a = sX[r8 * 64 + k];
            float4 q0 = ((const float4*)(sQ + k * 64))[g8 * 2];
            float4 q1 = ((const float4*)(sQ + k * 64))[g8 * 2 + 1];
            acc[0] += a * q0.x; acc[1] += a * q0.y; acc[2] += a * q0.z; acc[3] += a * q0.w;
            acc[4] += a * q1.x; acc[5] += a * q1.y; acc[6] += a * q1.z; acc[7] += a * q1.w;
        }
        __syncthreads();   // all reads of sX done
        #pragma unroll
        for (int m = 0; m < 8; m++) sX[r8 * 64 + g8 * 8 + m] = acc[m];
        __syncthreads();
    }
    // sX = Yinv

    // sN = Yinv^T
    for (int e = tid; e < 4096; e += 512) {
        int i = e >> 6, j = e & 63;
        sN[j * 64 + i] = sX[e];
    }
    __syncthreads();

    const float linv = 1.0f / lambdas[r8];

    // x rows: Atil[j][k] = sum_i YinvT[j][i] A[i][k]; B2til likewise (j=r8)
    {
        float accA[8], accB[8];
        #pragma unroll
        for (int m = 0; m < 8; m++) { accA[m] = 0.0f; accB[m] = 0.0f; }
        for (int i = 0; i < 64; i++) {
            float yt = sN[r8 * 64 + i];
            float4 a0 = ((const float4*)(A + i * 64))[g8 * 2];
            float4 a1 = ((const float4*)(A + i * 64))[g8 * 2 + 1];
            float4 b0 = ((const float4*)(B2 + i * 64))[g8 * 2];
            float4 b1 = ((const float4*)(B2 + i * 64))[g8 * 2 + 1];
            accA[0] += yt * a0.x; accA[1] += yt * a0.y; accA[2] += yt * a0.z; accA[3] += yt * a0.w;
            accA[4] += yt * a1.x; accA[5] += yt * a1.y; accA[6] += yt * a1.z; accA[7] += yt * a1.w;
            accB[0] += yt * b0.x; accB[1] += yt * b0.y; accB[2] += yt * b0.z; accB[3] += yt * b0.w;
            accB[4] += yt * b1.x; accB[5] += yt * b1.y; accB[6] += yt * b1.z; accB[7] += yt * b1.w;
        }
        #pragma unroll
        for (int m = 0; m < 8; m++) {
            gW[(64 + r8) * 192 + g8 * 8 + m]      = accA[m];
            gW[(64 + r8) * 192 + 64 + g8 * 8 + m] = accB[m];
        }
    }
    // B1til: 64x32 (4-col groups)
    {
        float a4[4] = {0.f, 0.f, 0.f, 0.f};
        for (int i = 0; i < 64; i++) {
            float yt = sN[r8 * 64 + i];
            float4 b = ((const float4*)(B1 + i * 32))[g8];
            a4[0] += yt * b.x; a4[1] += yt * b.y; a4[2] += yt * b.z; a4[3] += yt * b.w;
        }
        #pragma unroll
        for (int m = 0; m < 4; m++)
            gW[(64 + r8) * 192 + 128 + g8 * 4 + m] = a4[m];
    }
    // H[z][i] = sum_j (C2[z][j]/lam_z) YinvT[j][i]  -> sQ
    {
        float acc[8];
        #pragma unroll
        for (int m = 0; m < 8; m++) acc[m] = 0.0f;
        for (int j = 0; j < 64; j++) {
            float c = C2[r8 * 64 + j] * linv;
            float4 y0 = ((const float4*)(sN + j * 64))[g8 * 2];
            float4 y1 = ((const float4*)(sN + j * 64))[g8 * 2 + 1];
            acc[0] += c * y0.x; acc[1] += c * y0.y; acc[2] += c * y0.z; acc[3] += c * y0.w;
            acc[4] += c * y1.x; acc[5] += c * y1.y; acc[6] += c * y1.z; acc[7] += c * y1.w;
        }
        #pragma unroll
        for (int m = 0; m < 8; m++) sQ[r8 * 64 + g8 * 8 + m] = acc[m];
    }
    __syncthreads();
    // Gzx = H@A, Gzw = H@B2
    {
        float accX[8], accW[8];
        #pragma unroll
        for (int m = 0; m < 8; m++) { accX[m] = 0.0f; accW[m] = 0.0f; }
        for (int i = 0; i < 64; i++) {
            float hh = sQ[r8 * 64 + i];
            float4 a0 = ((const float4*)(A + i * 64))[g8 * 2];
            float4 a1 = ((const float4*)(A + i * 64))[g8 * 2 + 1];
            float4 b0 = ((const float4*)(B2 + i * 64))[g8 * 2];
            float4 b1 = ((const float4*)(B2 + i * 64))[g8 * 2 + 1];
            accX[0] += hh * a0.x; accX[1] += hh * a0.y; accX[2] += hh * a0.z; accX[3] += hh * a0.w;
            accX[4] += hh * a1.x; accX[5] += hh * a1.y; accX[6] += hh * a1.z; accX[7] += hh * a1.w;
            accW[0] += hh * b0.x; accW[1] += hh * b0.y; accW[2] += hh * b0.z; accW[3] += hh * b0.w;
            accW[4] += hh * b1.x; accW[5] += hh * b1.y; accW[6] += hh * b1.z; accW[7] += hh * b1.w;
        }
        #pragma unroll
        for (int m = 0; m < 8; m++) {
            gW[r8 * 192 + g8 * 8 + m]      = accX[m];
            gW[r8 * 192 + 64 + g8 * 8 + m] = accW[m];
        }
    }
    // Gzu = H@B1
    {
        float a4[4] = {0.f, 0.f, 0.f, 0.f};
        for (int i = 0; i < 64; i++) {
            float hh = sQ[r8 * 64 + i];
            float4 b = ((const float4*)(B1 + i * 32))[g8];
            a4[0] += hh * b.x; a4[1] += hh * b.y; a4[2] += hh * b.z; a4[3] += hh * b.w;
        }
        #pragma unroll
        for (int m = 0; m < 4; m++)
            gW[r8 * 192 + 128 + g8 * 4 + m] = a4[m];
    }
    // D21t
    for (int e = tid; e < 64 * 32; e += 512) {
        int z = e >> 5, m = e & 31;
        gW[z * 192 + 160 + m] = D21[e] / lambdas[z];
    }
    // y rows
    for (int e = tid; e < 32 * 64; e += 512) {
        int j = e >> 6, k = e & 63;
        gW[(128 + j) * 192 + k]      = C1[e];
        gW[(128 + j) * 192 + 64 + k] = D12[e];
    }
    for (int e = tid; e < 32 * 32; e += 512) {
        int j = e >> 5, m = e & 31;
        gW[(128 + j) * 192 + 128 + m] = D11[e];
    }
    __syncthreads();

    // pack gWT
    for (int s = tid; s < 320; s += 512) {
        if (s < 128) {
            int row = s >> 1, h = s & 1;
            for (int i = 0; i < 24; i++) {
                int c;
                if (i < 16)      c = h + 2 * i;
                else if (i < 20) c = 32 + h + 2 * (i - 16);
                else             c = 40 + h + 2 * (i - 20);
                #pragma unroll
                for (int j = 0; j < 4; j++)
                    gWT[s * 96 + 4 * i + j] = gW[row * 192 + 4 * c + j];
            }
        } else {
            int idx, row;
            if (s < 256) { idx = s - 128; row = 64 + (idx >> 1); }
            else         { idx = s - 256; row = 128 + (idx >> 1); }
            int h = idx & 1;
            for (int i = 0; i < 20; i++) {
                int c = (i < 16) ? (h + 2 * i) : (32 + h + 2 * (i - 16));
                #pragma unroll
                for (int j = 0; j < 4; j++)
                    gWT[s * 96 + 4 * i + j] = gW[row * 192 + 4 * c + j];
            }
        }
    }
}

// ---------------------------------------------------------------------------
// helpers
// ---------------------------------------------------------------------------
__device__ __forceinline__ float2 u64_as_f2(unsigned long long x) {
    float2 r;
    asm("mov.b64 {%0, %1}, %2;" : "=f"(r.x), "=f"(r.y) : "l"(x));
    return r;
}
#define FFMA2(acc, w, vv) \
    asm("fma.rn.f32x2 %0, %1, %2, %0;" : "+l"(acc) : "l"(w), "l"(vv))
#define ADDF2(d, a, b) \
    asm("add.rn.f32x2 %0, %1, %2;" : "=l"(d) : "l"(a), "l"(b))
#define BARB(id) asm volatile("bar.sync %0, 256;" :: "r"(id) : "memory")

__device__ __forceinline__ float fast_tanh(float x) {
    float e;
    asm("ex2.approx.f32 %0, %1;" : "=f"(e) : "f"(x * 2.8853900817779268f));
    return 1.0f - __fdividef(2.0f, e + 1.0f);
}

// ---------------------------------------------------------------------------
// Sequential kernel: 128 CTAs x 512 threads, 2 batch chains per CTA,
// ONE barrier per step (z substituted: w_{t+1} = tanh(Gzx x_t + Gzw w_t + pu)).
// Per batch 256 threads: 128 z-halves + 128 x-halves; u-partials pipelined.
// smem per batch: vx[2][64] | vw[2][64] | vu[4][32] (double/ring buffered).
// Streams [x_t|w_t] to gVseq for the decoupled y-pass.
// batch=(wid>>2)&1, isZ=wid>=8, widx=wid&3 -> every SMSP: 2 z + 2 x warps.
// ---------------------------------------------------------------------------
__global__ void __launch_bounds__(512, 1)
rnn_kernel(const float* __restrict__ xpred, float* __restrict__ out, int write_xfinal)
{
    __shared__ __align__(16) float sv[2 * 384];

    const int tid  = threadIdx.x;
    const int wid  = tid >> 5;
    const int lane = tid & 31;

    const int isZ   = (wid >= 8);
    const int batch = (wid >> 2) & 1;
    const int widx  = wid & 3;
    const int idx   = widx * 32 + lane;   // 0..127
    const int row   = idx >> 1;           // 0..63
    const int h     = idx & 1;

    float* vbase = sv + batch * 384;      // vx2 [0:128) | vw2 [128:256) | vu [256:384)
    const int bg = blockIdx.x * 2 + batch;
    const float* uptr = xpred + (size_t)bg * TT * NU;
    float* gv = gVseq + (size_t)bg * (TT + 1) * 128;
    const int barid = batch + 1;

    if (isZ) {
        // ================= Z half: 24 chunks ==============================
        unsigned long long wreg[48];
        {
            const unsigned long long* grow = (const unsigned long long*)(gWT + idx * 96);
            #pragma unroll
            for (int i = 0; i < 48; i++) wreg[i] = grow[i];
        }
        BARB(barid);   // u_0..u_2 staged, vx[0] zeroed

        // prologue: z_0 = D21t u_0 (i20..23 over slot 0); w_0
        {
            const float* u0p = vbase + 256 + 4 * h;
            unsigned long long b0 = 0ull, b1 = 0ull;
            #pragma unroll
            for (int i = 20; i < 24; i += 2) {
                ulonglong2 q0 = *(const ulonglong2*)(u0p + 8 * (i - 20));
                ulonglong2 q1 = *(const ulonglong2*)(u0p + 8 * (i - 20) + 8);
                FFMA2(b0, wreg[2*i],   q0.x); FFMA2(b1, wreg[2*i+1], q0.y);
                FFMA2(b0, wreg[2*i+2], q1.x); FFMA2(b1, wreg[2*i+3], q1.y);
            }
            ADDF2(b0, b0, b1);
            float2 pp = u64_as_f2(b0);
            float zs = pp.x + pp.y;
            zs += __shfl_xor_sync(0xffffffffu, zs, 1);
            float w0 = fast_tanh(zs);
            if (h == 0) {
                vbase[128 + row] = w0;     // vw buf 0
                gv[64 + row] = w0;         // stream w_0
            }
        }
        // pu for phase 0: Gzu u_0 (slot0) + D21t u_1 (slot1)
        unsigned long long pu;
        {
            const float* ua = vbase + 256 + 4 * h;          // slot 0
            const float* ub = vbase + 256 + 32 + 4 * h;     // slot 1
            unsigned long long b0 = 0ull, b1 = 0ull;
            #pragma unroll
            for (int i = 16; i < 20; i += 2) {
                ulonglong2 q0 = *(const ulonglong2*)(ua + 8 * (i - 16));
                ulonglong2 q1 = *(const ulonglong2*)(ua + 8 * (i - 16) + 8);
                FFMA2(b0, wreg[2*i],   q0.x); FFMA2(b1, wreg[2*i+1], q0.y);
                FFMA2(b0, wreg[2*i+2], q1.x); FFMA2(b1, wreg[2*i+3], q1.y);
            }
            #pragma unroll
            for (int i = 20; i < 24; i += 2) {
                ulonglong2 q0 = *(const ulonglong2*)(ub + 8 * (i - 20));
                ulonglong2 q1 = *(const ulonglong2*)(ub + 8 * (i - 20) + 8);
                FFMA2(b0, wreg[2*i],   q0.x); FFMA2(b1, wreg[2*i+1], q0.y);
                FFMA2(b0, wreg[2*i+2], q1.x); FFMA2(b1, wreg[2*i+3], q1.y);
            }
            ADDF2(pu, b0, b1);
        }
        BARB(barid);

        for (int t = 0; t < TT; t++) {
            const int p = t & 1;
            const float* vxp = vbase + p * 64 + 4 * h;
            const float* vwp = vbase + 128 + p * 64 + 4 * h;
            unsigned long long a0=0ull,a1=0ull,a2=0ull,a3=0ull;
            #pragma unroll
            for (int i = 0; i < 8; i += 2) {
                ulonglong2 v0 = *(const ulonglong2*)(vxp + 8 * i);
                ulonglong2 v1 = *(const ulonglong2*)(vxp + 8 * i + 8);
                FFMA2(a0, wreg[2*i],   v0.x); FFMA2(a1, wreg[2*i+1], v0.y);
                FFMA2(a2, wreg[2*i+2], v1.x); FFMA2(a3, wreg[2*i+3], v1.y);
            }
            #pragma unroll
            for (int i = 8; i < 16; i += 2) {
                ulonglong2 v0 = *(const ulonglong2*)(vwp + 8 * (i - 8));
                ulonglong2 v1 = *(const ulonglong2*)(vwp + 8 * (i - 8) + 8);
                FFMA2(a0, wreg[2*i],   v0.x); FFMA2(a1, wreg[2*i+1], v0.y);
                FFMA2(a2, wreg[2*i+2], v1.x); FFMA2(a3, wreg[2*i+3], v1.y);
            }
            ADDF2(a0, a0, a2); ADDF2(a1, a1, a3);
            ADDF2(a0, a0, a1); ADDF2(a0, a0, pu);
            float2 pp = u64_as_f2(a0);
            float zs = pp.x + pp.y;
            zs += __shfl_xor_sync(0xffffffffu, zs, 1);
            float w = fast_tanh(zs);
            if (h == 0) {
                vbase[128 + (p ^ 1) * 64 + row] = w;        // publish w_{t+1}
                gv[(size_t)(t + 1) * 128 + 64 + row] = w;   // stream
            }
            // pu for next: Gzu u_{t+1} + D21t u_{t+2}
            {
                const float* ua = vbase + 256 + ((t + 1) & 3) * 32 + 4 * h;
                const float* ub = vbase + 256 + ((t + 2) & 3) * 32 + 4 * h;
                unsigned long long b0 = 0ull, b1 = 0ull;
                #pragma unroll
                for (int i = 16; i < 20; i += 2) {
                    ulonglong2 q0 = *(const ulonglong2*)(ua + 8 * (i - 16));
                    ulonglong2 q1 = *(const ulonglong2*)(ua + 8 * (i - 16) + 8);
                    FFMA2(b0, wreg[2*i],   q0.x); FFMA2(b1, wreg[2*i+1], q0.y);
                    FFMA2(b0, wreg[2*i+2], q1.x); FFMA2(b1, wreg[2*i+3], q1.y);
                }
                #pragma unroll
                for (int i = 20; i < 24; i += 2) {
                    ulonglong2 q0 = *(const ulonglong2*)(ub + 8 * (i - 20));
                    ulonglong2 q1 = *(const ulonglong2*)(ub + 8 * (i - 20) + 8);
                    FFMA2(b0, wreg[2*i],   q0.x); FFMA2(b1, wreg[2*i+1], q0.y);
                    FFMA2(b0, wreg[2*i+2], q1.x); FFMA2(b1, wreg[2*i+3], q1.y);
                }
                ADDF2(pu, b0, b1);
            }
            BARB(barid);
        }
    } else {
        // ================= X half: 20 chunks ==============================
        unsigned long long wreg[40];
        {
            const unsigned long long* grow = (const unsigned long long*)(gWT + (128 + idx) * 96);
            #pragma unroll
            for (int i = 0; i < 40; i++) wreg[i] = grow[i];
        }
        const bool stager = (widx == 0);
        float u_next = 0.0f;
        if (h == 0) {
            vbase[row] = 0.0f;    // x_0 buf 0
            gv[row] = 0.0f;       // stream x_0
        }
        if (stager) {
            vbase[256 + lane]      = uptr[lane];            // u_0
            vbase[256 + 32 + lane] = uptr[NU + lane];       // u_1
            vbase[256 + 64 + lane] = uptr[2 * NU + lane];   // u_2
            u_next = uptr[3 * NU + lane];                   // u_3
        }
        BARB(barid);

        // pu for phase 0: B1til u_0 (slot 0)
        unsigned long long pu;
        {
            const float* ua = vbase + 256 + 4 * h;
            unsigned long long b0 = 0ull, b1 = 0ull;
            #pragma unroll
            for (int i = 16; i < 20; i += 2) {
                ulonglong2 q0 = *(const ulonglong2*)(ua + 8 * (i - 16));
                ulonglong2 q1 = *(const ulonglong2*)(ua + 8 * (i - 16) + 8);
                FFMA2(b0, wreg[2*i],   q0.x); FFMA2(b1, wreg[2*i+1], q0.y);
                FFMA2(b0, wreg[2*i+2], q1.x); FFMA2(b1, wreg[2*i+3], q1.y);
            }
            ADDF2(pu, b0, b1);
        }
        BARB(barid);

        for (int t = 0; t < TT; t++) {
            const int p = t & 1;
            const float* vxp = vbase + p * 64 + 4 * h;
            const float* vwp = vbase + 128 + p * 64 + 4 * h;
            unsigned long long a0=0ull,a1=0ull,a2=0ull,a3=0ull;
            #pragma unroll
            for (int i = 0; i < 8; i += 2) {
                ulonglong2 v0 = *(const ulonglong2*)(vxp + 8 * i);
                ulonglong2 v1 = *(const ulonglong2*)(vxp + 8 * i + 8);
                FFMA2(a0, wreg[2*i],   v0.x); FFMA2(a1, wreg[2*i+1], v0.y);
                FFMA2(a2, wreg[2*i+2], v1.x); FFMA2(a3, wreg[2*i+3], v1.y);
            }
            #pragma unroll
            for (int i = 8; i < 16; i += 2) {
                ulonglong2 v0 = *(const ulonglong2*)(vwp + 8 * (i - 8));
                ulonglong2 v1 = *(const ulonglong2*)(vwp + 8 * (i - 8) + 8);
                FFMA2(a0, wreg[2*i],   v0.x); FFMA2(a1, wreg[2*i+1], v0.y);
                FFMA2(a2, wreg[2*i+2], v1.x); FFMA2(a3, wreg[2*i+3], v1.y);
            }
            ADDF2(a0, a0, a2); ADDF2(a1, a1, a3);
            ADDF2(a0, a0, a1); ADDF2(a0, a0, pu);
            float2 pp = u64_as_f2(a0);
            float acc = pp.x + pp.y;
            acc += __shfl_xor_sync(0xffffffffu, acc, 1);
            if (h == 0) {
                vbase[(p ^ 1) * 64 + row] = acc;            // publish x_{t+1}
                gv[(size_t)(t + 1) * 128 + row] = acc;      // stream
            }
            if (stager) {
                vbase[256 + ((t + 3) & 3) * 32 + lane] = u_next;
                if (t + 4 < TT) u_next = uptr[(size_t)(t + 4) * NU + lane];
            }
            // pu for next: B1til u_{t+1}
            {
                const float* ua = vbase + 256 + ((t + 1) & 3) * 32 + 4 * h;
                unsigned long long b0 = 0ull, b1 = 0ull;
                #pragma unroll
                for (int i = 16; i < 20; i += 2) {
                    ulonglong2 q0 = *(const ulonglong2*)(ua + 8 * (i - 16));
                    ulonglong2 q1 = *(const ulonglong2*)(ua + 8 * (i - 16) + 8);
                    FFMA2(b0, wreg[2*i],   q0.x); FFMA2(b1, wreg[2*i+1], q0.y);
                    FFMA2(b0, wreg[2*i+2], q1.x); FFMA2(b1, wreg[2*i+3], q1.y);
                }
                ADDF2(pu, b0, b1);
            }
            BARB(barid);
        }

        if (write_xfinal && h == 0) {
            // x_TT is in vx buffer (TT & 1) = 0
            out[(size_t)BB * TT * NY + (size_t)bg * NX + row] = vbase[row];
        }
    }
}

// ---------------------------------------------------------------------------
// y-pass: weight-persistent, 16-timestep rounds (MLP-amortized staging).
// Grid (BB, 4), 256 threads, 2 CTAs/SM. Thread = (g in 0..3, j, h); each
// (g,j,h) computes 4 timesteps per round; y half-row (40 u64) in registers.
// ---------------------------------------------------------------------------
__global__ void __launch_bounds__(256, 2)
ypass_kernel(const float* __restrict__ xpred, float* __restrict__ out)
{
    __shared__ __align__(16) float sv2[16 * 160];

    const int b   = blockIdx.x;
    const int seg = blockIdx.y;       // 0..3 -> t range [seg*512, seg*512+512)
    const int tid = threadIdx.x;
    const int g = tid >> 6;           // 0..3
    const int q = tid & 63;
    const int j = q >> 1, h = q & 1;

    const float4* gv4 = (const float4*)(gVseq + (size_t)b * (TT + 1) * 128);
    const float4* u4  = (const float4*)(xpred + (size_t)b * TT * NU);
    float* yout = out + (size_t)b * TT * NY;

    unsigned long long wreg[40];
    {
        const unsigned long long* grow = (const unsigned long long*)(gWT + (256 + q) * 96);
        #pragma unroll
        for (int i = 0; i < 40; i++) wreg[i] = grow[i];
    }

    for (int rnd = 0; rnd < 32; rnd++) {
        const int t0 = seg * 512 + rnd * 16;
        // stage 16 timesteps: [x|w] (32 f4) + u (8 f4) each
        for (int e = tid; e < 640; e += 256) {
            int tl = e / 40, k = e - tl * 40;
            float4 val = (k < 32) ? gv4[(size_t)(t0 + tl) * 32 + k]
                                  : u4[(size_t)(t0 + tl) * 8 + (k - 32)];
            *(float4*)(sv2 + tl * 160 + 4 * k) = val;
        }
        __syncthreads();

        #pragma unroll
        for (int m = 0; m < 4; m++) {
            const int tl = g + 4 * m;
            const float* vh = sv2 + tl * 160 + 4 * h;
            unsigned long long a0=0ull,a1=0ull,a2=0ull,a3=0ull;
            #pragma unroll
            for (int i = 0; i < 16; i += 2) {
                ulonglong2 v0 = *(const ulonglong2*)(vh + 8 * i);
                ulonglong2 v1 = *(const ulonglong2*)(vh + 8 * i + 8);
                FFMA2(a0, wreg[2*i],   v0.x); FFMA2(a1, wreg[2*i+1], v0.y);
                FFMA2(a2, wreg[2*i+2], v1.x); FFMA2(a3, wreg[2*i+3], v1.y);
            }
            #pragma unroll
            for (int i = 16; i < 20; i += 2) {
                ulonglong2 v0 = *(const ulonglong2*)(vh + 128 + 8 * (i - 16));
                ulonglong2 v1 = *(const ulonglong2*)(vh + 128 + 8 * (i - 16) + 8);
                FFMA2(a0, wreg[2*i],   v0.x); FFMA2(a1, wreg[2*i+1], v0.y);
                FFMA2(a2, wreg[2*i+2], v1.x); FFMA2(a3, wreg[2*i+3], v1.y);
            }
            ADDF2(a0, a0, a2); ADDF2(a1, a1, a3); ADDF2(a0, a0, a1);
            float2 pp = u64_as_f2(a0);
            float acc = pp.x + pp.y;
            acc += __shfl_xor_sync(0xffffffffu, acc, 1);
            if (h == 0) yout[(size_t)(t0 + tl) * NY + j] = acc;
        }
        __syncthreads();
    }
}

// ---------------------------------------------------------------------------
extern "C" void kernel_launch(void* const* d_in, const int* in_sizes, int n_in,
                              void* d_out, int out_size)
{
    const float* xpred   = (const float*)d_in[0];
    const float* Y       = (const float*)d_in[1];
    const float* lambdas = (const float*)d_in[2];
    const float* A       = (const float*)d_in[3];
    const float* B1      = (const float*)d_in[4];
    const float* B2      = (const float*)d_in[5];
    const float* C1      = (const float*)d_in[6];
    const float* D11     = (const float*)d_in[7];
    const float* D12     = (const float*)d_in[8];
    const float* C2      = (const float*)d_in[9];
    const float* D21     = (const float*)d_in[10];

    (void)in_sizes; (void)n_in;

    setup_kernel<<<1, 512>>>(Y, lambdas, A, B1, B2, C1, D11, D12, C2, D21);

    int write_xfinal = (out_size >= BB * TT * NY + BB * NX) ? 1 : 0;
    rnn_kernel<<<BB / 2, 512>>>(xpred, (float*)d_out, write_xfinal);

    dim3 ygrid(BB, 4);
    ypass_kernel<<<ygrid, 256>>>(xpred, (float*)d_out);
}